// round 7
// baseline (speedup 1.0000x reference)
#include <cuda_runtime.h>
#include <cuda_bf16.h>
#include <mma.h>
#include <cstdint>

using namespace nvcuda;

// ---------------------------------------------------------------------------
// GraphSAGE 3-layer. Transform-then-aggregate + CSR gather.
// GEMMs run on tensor cores via bf16 Markidis split (hi/lo):
//   x*w ~= xh*wh + xh*wl + xl*wh   (error ~2^-17, tolerance is 1e-3)
// Dual-output GEMM (Wl & Wr share converted X tile); epilogue of layers 0/1
// folded into next layer's GEMM prologue. CSR build overlaps on aux stream.
// ---------------------------------------------------------------------------

#define N_NODES 100000
#define N_EDGES 1600000

__device__ float g_yl[(size_t)N_NODES * 128];
__device__ float g_yr[(size_t)N_NODES * 128];
__device__ float g_bufA[(size_t)N_NODES * 128];   // agg
__device__ float g_bufB[(size_t)N_NODES * 128];   // agg
__device__ int   g_cnt[N_NODES];
__device__ int   g_off[N_NODES];
__device__ int   g_cur[N_NODES];
__device__ int   g_csr[N_EDGES];
__device__ int   g_bsum[128];
__device__ int   g_is64;
__device__ __nv_bfloat16 g_whi[6 * 16384];
__device__ __nv_bfloat16 g_wlo[6 * 16384];

// --------------------------- edge dtype probe ------------------------------
__global__ void detect_kernel(const void* ei) {
    const long long* e64 = (const long long*)ei;
    int is64 = 1;
    for (int i = 0; i < 64; i++) {
        long long v = e64[i];
        if (v < 0 || v >= N_NODES) { is64 = 0; break; }
    }
    g_is64 = is64;
}

__device__ __forceinline__ int load_idx(const void* ei, long long pos) {
    if (g_is64) return (int)((const long long*)ei)[pos];
    return ((const int*)ei)[pos];
}

// ------------------------------- CSR build ---------------------------------
__global__ void zero_int_kernel(int* __restrict__ p, int n) {
    int i = blockIdx.x * blockDim.x + threadIdx.x;
    if (i < n) p[i] = 0;
}

__global__ void hist_kernel(const void* __restrict__ ei, int* __restrict__ cnt) {
    int e = blockIdx.x * blockDim.x + threadIdx.x;
    if (e < N_EDGES) {
        int d = load_idx(ei, (long long)N_EDGES + e);
        if ((unsigned)d < N_NODES) atomicAdd(&cnt[d], 1);
    }
}

__global__ void blockreduce_kernel(const int* __restrict__ cnt, int* __restrict__ bsum) {
    __shared__ int sm[256];
    int b = blockIdx.x, t = threadIdx.x;
    int base = b * 1024 + t * 4;
    int s = 0;
    #pragma unroll
    for (int i = 0; i < 4; i++) {
        int idx = base + i;
        if (idx < N_NODES) s += cnt[idx];
    }
    sm[t] = s; __syncthreads();
    for (int st = 128; st > 0; st >>= 1) {
        if (t < st) sm[t] += sm[t + st];
        __syncthreads();
    }
    if (t == 0) bsum[b] = sm[0];
}

__global__ void scanpart_kernel(int* __restrict__ bsum, int nb) {
    if (threadIdx.x == 0) {
        int acc = 0;
        for (int i = 0; i < nb; i++) { int v = bsum[i]; bsum[i] = acc; acc += v; }
    }
}

__global__ void scanfinal_kernel(const int* __restrict__ cnt, const int* __restrict__ bsum,
                                 int* __restrict__ off, int* __restrict__ cur) {
    __shared__ int sm[256];
    int b = blockIdx.x, t = threadIdx.x;
    int base = b * 1024 + t * 4;
    int v[4]; int s = 0;
    #pragma unroll
    for (int i = 0; i < 4; i++) {
        int idx = base + i;
        v[i] = (idx < N_NODES) ? cnt[idx] : 0;
        s += v[i];
    }
    sm[t] = s; __syncthreads();
    for (int st = 1; st < 256; st <<= 1) {
        int x = (t >= st) ? sm[t - st] : 0;
        __syncthreads();
        sm[t] += x;
        __syncthreads();
    }
    int run = sm[t] - s + bsum[b];
    #pragma unroll
    for (int i = 0; i < 4; i++) {
        int idx = base + i;
        if (idx < N_NODES) { off[idx] = run; cur[idx] = run; }
        run += v[i];
    }
}

__global__ void fill_kernel(const void* __restrict__ ei, int* __restrict__ cur,
                            int* __restrict__ csr) {
    int e = blockIdx.x * blockDim.x + threadIdx.x;
    if (e < N_EDGES) {
        int s = load_idx(ei, e);
        int d = load_idx(ei, (long long)N_EDGES + e);
        if ((unsigned)s < N_NODES && (unsigned)d < N_NODES) {
            int p = atomicAdd(&cur[d], 1);
            csr[p] = s;
        }
    }
}

// --------------------- weight split (fp32 -> bf16 hi/lo) -------------------
__global__ void wsplit_kernel(const float* __restrict__ W,
                              __nv_bfloat16* __restrict__ hi,
                              __nv_bfloat16* __restrict__ lo, int n) {
    int i = blockIdx.x * blockDim.x + threadIdx.x;
    if (i < n) {
        float w = W[i];
        __nv_bfloat16 h = __float2bfloat16(w);
        hi[i] = h;
        lo[i] = __float2bfloat16(w - __bfloat162float(h));
    }
}

// ---------------------------------------------------------------------------
// Dual tensor-core GEMM: Yl = H@Wl, Yr = H@Wr  (H: [N,128], W: [128,DOUT])
// H is X (PRO=false) or relu(agg/max(deg,1) + yrIn + bias) (PRO=true),
// split into bf16 hi/lo in smem. W fragments read straight from gmem (L1/L2
// resident). Block: 128 rows, 256 threads (8 warps).
// ---------------------------------------------------------------------------
#define LDXS 136   // smem leading dim (bf16 elems)

__device__ __forceinline__ void split2(float a, float b, __nv_bfloat162& h2, __nv_bfloat162& l2) {
    __nv_bfloat16 ha = __float2bfloat16(a), hb = __float2bfloat16(b);
    h2 = __nv_bfloat162(ha, hb);
    l2 = __nv_bfloat162(__float2bfloat16(a - __bfloat162float(ha)),
                        __float2bfloat16(b - __bfloat162float(hb)));
}

template <int DOUT, bool PRO>
__global__ __launch_bounds__(256) void gemm_dual_bf16(
    const float* __restrict__ X,
    const float* __restrict__ agg, const float* __restrict__ yrIn,
    const int* __restrict__ cnt, const float* __restrict__ bias,
    const __nv_bfloat16* __restrict__ Wlhi, const __nv_bfloat16* __restrict__ Wllo,
    const __nv_bfloat16* __restrict__ Wrhi, const __nv_bfloat16* __restrict__ Wrlo,
    float* __restrict__ Yl, float* __restrict__ Yr)
{
    extern __shared__ __nv_bfloat16 smem[];
    __nv_bfloat16* sXhi = smem;                 // [128][LDXS]
    __nv_bfloat16* sXlo = smem + 128 * LDXS;    // [128][LDXS]

    const int row0 = blockIdx.x * 128;
    const int t = threadIdx.x;

    // ---- prologue: build H tile, split to bf16 hi/lo ----
    for (int i = t; i < 128 * 32; i += 256) {
        int r = i >> 5, c4 = i & 31;
        int gr = row0 + r;
        float4 v = make_float4(0.f, 0.f, 0.f, 0.f);
        if (gr < N_NODES) {
            if (PRO) {
                float4 a  = reinterpret_cast<const float4*>(agg)[(size_t)gr * 32 + c4];
                float4 yv = reinterpret_cast<const float4*>(yrIn)[(size_t)gr * 32 + c4];
                float4 bb = reinterpret_cast<const float4*>(bias)[c4];
                float dinv = 1.0f / fmaxf((float)cnt[gr], 1.0f);
                v.x = fmaxf(a.x * dinv + yv.x + bb.x, 0.f);
                v.y = fmaxf(a.y * dinv + yv.y + bb.y, 0.f);
                v.z = fmaxf(a.z * dinv + yv.z + bb.z, 0.f);
                v.w = fmaxf(a.w * dinv + yv.w + bb.w, 0.f);
            } else {
                v = reinterpret_cast<const float4*>(X + (size_t)gr * 128)[c4];
            }
        }
        __nv_bfloat162 h0, l0, h1, l1;
        split2(v.x, v.y, h0, l0);
        split2(v.z, v.w, h1, l1);
        int base = r * LDXS + c4 * 4;
        *reinterpret_cast<__nv_bfloat162*>(&sXhi[base])     = h0;
        *reinterpret_cast<__nv_bfloat162*>(&sXhi[base + 2]) = h1;
        *reinterpret_cast<__nv_bfloat162*>(&sXlo[base])     = l0;
        *reinterpret_cast<__nv_bfloat162*>(&sXlo[base + 2]) = l1;
    }
    __syncthreads();

    // ---- warp tiling ----
    constexpr int WN = DOUT / 64;       // warps along n (2 or 1)
    constexpr int WM = 8 / WN;          // warps along m (4 or 8)
    constexpr int MFRAG = 128 / (WM * 16); // 2 or 1
    const int warp = t >> 5;
    const int wm = warp % WM;
    const int wn = warp / WM;
    const int mbase = wm * MFRAG * 16;
    const int nbase = wn * 64;

    wmma::fragment<wmma::accumulator, 16, 16, 16, float> accl[MFRAG][4], accr[MFRAG][4];
    #pragma unroll
    for (int mf = 0; mf < MFRAG; mf++)
        #pragma unroll
        for (int nf = 0; nf < 4; nf++) {
            wmma::fill_fragment(accl[mf][nf], 0.0f);
            wmma::fill_fragment(accr[mf][nf], 0.0f);
        }

    #pragma unroll
    for (int k = 0; k < 128; k += 16) {
        wmma::fragment<wmma::matrix_a, 16, 16, 16, __nv_bfloat16, wmma::row_major> ahi[MFRAG], alo[MFRAG];
        #pragma unroll
        for (int mf = 0; mf < MFRAG; mf++) {
            wmma::load_matrix_sync(ahi[mf], &sXhi[(mbase + mf * 16) * LDXS + k], LDXS);
            wmma::load_matrix_sync(alo[mf], &sXlo[(mbase + mf * 16) * LDXS + k], LDXS);
        }
        #pragma unroll
        for (int nf = 0; nf < 4; nf++) {
            int n0 = nbase + nf * 16;
            wmma::fragment<wmma::matrix_b, 16, 16, 16, __nv_bfloat16, wmma::row_major> bhl, bll, bhr, blr;
            wmma::load_matrix_sync(bhl, Wlhi + k * DOUT + n0, DOUT);
            wmma::load_matrix_sync(bll, Wllo + k * DOUT + n0, DOUT);
            wmma::load_matrix_sync(bhr, Wrhi + k * DOUT + n0, DOUT);
            wmma::load_matrix_sync(blr, Wrlo + k * DOUT + n0, DOUT);
            #pragma unroll
            for (int mf = 0; mf < MFRAG; mf++) {
                wmma::mma_sync(accl[mf][nf], ahi[mf], bhl, accl[mf][nf]);
                wmma::mma_sync(accl[mf][nf], ahi[mf], bll, accl[mf][nf]);
                wmma::mma_sync(accl[mf][nf], alo[mf], bhl, accl[mf][nf]);
                wmma::mma_sync(accr[mf][nf], ahi[mf], bhr, accr[mf][nf]);
                wmma::mma_sync(accr[mf][nf], ahi[mf], blr, accr[mf][nf]);
                wmma::mma_sync(accr[mf][nf], alo[mf], bhr, accr[mf][nf]);
            }
        }
    }

    // ---- store (N_NODES is 16-aligned -> whole-fragment guard) ----
    #pragma unroll
    for (int mf = 0; mf < MFRAG; mf++) {
        int grow = row0 + mbase + mf * 16;
        if (grow < N_NODES) {
            #pragma unroll
            for (int nf = 0; nf < 4; nf++) {
                wmma::store_matrix_sync(Yl + (size_t)grow * DOUT + nbase + nf * 16,
                                        accl[mf][nf], DOUT, wmma::mem_row_major);
                wmma::store_matrix_sync(Yr + (size_t)grow * DOUT + nbase + nf * 16,
                                        accr[mf][nf], DOUT, wmma::mem_row_major);
            }
        }
    }
}

// ---------------------------------------------------------------------------
// Agg-only gathers: agg[n] = sum_{s in N(n)} yl[s]
// ---------------------------------------------------------------------------
__global__ __launch_bounds__(256) void gather128_agg_kernel(
    const float* __restrict__ yl,
    const int* __restrict__ csr, const int* __restrict__ off,
    const int* __restrict__ cnt, float* __restrict__ agg)
{
    int warp = (blockIdx.x * 256 + threadIdx.x) >> 5;
    int lane = threadIdx.x & 31;
    if (warp >= N_NODES) return;

    const int c = cnt[warp];
    const int o = off[warp];
    const float4* __restrict__ yl4 = reinterpret_cast<const float4*>(yl);

    float4 acc = make_float4(0.f, 0.f, 0.f, 0.f);
    int j = 0;
    for (; j + 4 <= c; j += 4) {
        int s0 = csr[o + j + 0];
        int s1 = csr[o + j + 1];
        int s2 = csr[o + j + 2];
        int s3 = csr[o + j + 3];
        float4 a0 = yl4[(size_t)s0 * 32 + lane];
        float4 a1 = yl4[(size_t)s1 * 32 + lane];
        float4 a2 = yl4[(size_t)s2 * 32 + lane];
        float4 a3 = yl4[(size_t)s3 * 32 + lane];
        acc.x += a0.x + a1.x + a2.x + a3.x;
        acc.y += a0.y + a1.y + a2.y + a3.y;
        acc.z += a0.z + a1.z + a2.z + a3.z;
        acc.w += a0.w + a1.w + a2.w + a3.w;
    }
    for (; j < c; j++) {
        int s = csr[o + j];
        float4 a = yl4[(size_t)s * 32 + lane];
        acc.x += a.x; acc.y += a.y; acc.z += a.z; acc.w += a.w;
    }
    reinterpret_cast<float4*>(agg)[(size_t)warp * 32 + lane] = acc;
}

__global__ __launch_bounds__(256) void gather64_agg_kernel(
    const float* __restrict__ yl,
    const int* __restrict__ csr, const int* __restrict__ off,
    const int* __restrict__ cnt, float* __restrict__ agg)
{
    int node = (blockIdx.x * 256 + threadIdx.x) >> 4;
    int sub  = threadIdx.x & 15;
    if (node >= N_NODES) return;

    const int c = cnt[node];
    const int o = off[node];
    const float4* __restrict__ yl4 = reinterpret_cast<const float4*>(yl);

    float4 acc = make_float4(0.f, 0.f, 0.f, 0.f);
    int j = 0;
    for (; j + 4 <= c; j += 4) {
        int s0 = csr[o + j + 0];
        int s1 = csr[o + j + 1];
        int s2 = csr[o + j + 2];
        int s3 = csr[o + j + 3];
        float4 a0 = yl4[(size_t)s0 * 16 + sub];
        float4 a1 = yl4[(size_t)s1 * 16 + sub];
        float4 a2 = yl4[(size_t)s2 * 16 + sub];
        float4 a3 = yl4[(size_t)s3 * 16 + sub];
        acc.x += a0.x + a1.x + a2.x + a3.x;
        acc.y += a0.y + a1.y + a2.y + a3.y;
        acc.z += a0.z + a1.z + a2.z + a3.z;
        acc.w += a0.w + a1.w + a2.w + a3.w;
    }
    for (; j < c; j++) {
        int s = csr[o + j];
        float4 a = yl4[(size_t)s * 16 + sub];
        acc.x += a.x; acc.y += a.y; acc.z += a.z; acc.w += a.w;
    }
    reinterpret_cast<float4*>(agg)[(size_t)node * 16 + sub] = acc;
}

// ---------------------------------------------------------------------------
__global__ __launch_bounds__(256) void combine64_kernel(
    const float* __restrict__ agg, const float* __restrict__ yr,
    const float* __restrict__ b, const int* __restrict__ cnt,
    float* __restrict__ out)
{
    int i = blockIdx.x * blockDim.x + threadIdx.x;
    if (i >= N_NODES * 16) return;
    int node = i >> 4;
    int c4 = i & 15;

    float dinv = 1.0f / fmaxf((float)cnt[node], 1.0f);
    float4 a = reinterpret_cast<const float4*>(agg)[i];
    float4 r = reinterpret_cast<const float4*>(yr)[i];
    float4 bb = reinterpret_cast<const float4*>(b)[c4];

    float4 o;
    o.x = a.x * dinv + r.x + bb.x;
    o.y = a.y * dinv + r.y + bb.y;
    o.z = a.z * dinv + r.z + bb.z;
    o.w = a.w * dinv + r.w + bb.w;
    reinterpret_cast<float4*>(out)[i] = o;
}

// ---------------------------------------------------------------------------
extern "C" void kernel_launch(void* const* d_in, const int* in_sizes, int n_in,
                              void* d_out, int out_size)
{
    const float* x   = (const float*)d_in[0];
    const void*  ei  = d_in[1];
    const float* Wl0 = (const float*)d_in[2];
    const float* Wr0 = (const float*)d_in[3];
    const float* b0  = (const float*)d_in[4];
    const float* Wl1 = (const float*)d_in[5];
    const float* Wr1 = (const float*)d_in[6];
    const float* b1  = (const float*)d_in[7];
    const float* Wl2 = (const float*)d_in[8];
    const float* Wr2 = (const float*)d_in[9];
    const float* b2  = (const float*)d_in[10];
    float* out = (float*)d_out;

    const int SMEM_GEMM = 128 * LDXS * 2 * (int)sizeof(__nv_bfloat16);  // 69632

    static float *p_yl = nullptr, *p_yr = nullptr, *p_A = nullptr, *p_B = nullptr;
    static int *p_cnt = nullptr, *p_off = nullptr, *p_cur = nullptr, *p_csr = nullptr, *p_bsum = nullptr;
    static __nv_bfloat16 *p_whi = nullptr, *p_wlo = nullptr;
    static cudaStream_t s_aux = nullptr;
    static cudaEvent_t ev[4];
    if (!p_yl) {
        cudaGetSymbolAddress((void**)&p_yl,   g_yl);
        cudaGetSymbolAddress((void**)&p_yr,   g_yr);
        cudaGetSymbolAddress((void**)&p_A,    g_bufA);
        cudaGetSymbolAddress((void**)&p_B,    g_bufB);
        cudaGetSymbolAddress((void**)&p_cnt,  g_cnt);
        cudaGetSymbolAddress((void**)&p_off,  g_off);
        cudaGetSymbolAddress((void**)&p_cur,  g_cur);
        cudaGetSymbolAddress((void**)&p_csr,  g_csr);
        cudaGetSymbolAddress((void**)&p_bsum, g_bsum);
        cudaGetSymbolAddress((void**)&p_whi,  g_whi);
        cudaGetSymbolAddress((void**)&p_wlo,  g_wlo);
        cudaStreamCreateWithFlags(&s_aux, cudaStreamNonBlocking);
        for (int i = 0; i < 4; i++)
            cudaEventCreateWithFlags(&ev[i], cudaEventDisableTiming);
        cudaFuncSetAttribute(gemm_dual_bf16<128, false>,
                             cudaFuncAttributeMaxDynamicSharedMemorySize, SMEM_GEMM);
        cudaFuncSetAttribute(gemm_dual_bf16<128, true>,
                             cudaFuncAttributeMaxDynamicSharedMemorySize, SMEM_GEMM);
        cudaFuncSetAttribute(gemm_dual_bf16<64, true>,
                             cudaFuncAttributeMaxDynamicSharedMemorySize, SMEM_GEMM);
    }

    const int NB_GEMM  = (N_NODES + 127) / 128;          // 782
    const int NB_SCAN  = (N_NODES + 1023) / 1024;
    const int NB_EDGE  = (N_EDGES + 255) / 256;
    const int NB_G128  = (N_NODES * 32 + 255) / 256;
    const int NB_G64   = (N_NODES * 16 + 255) / 256;

    // Fork aux stream off the capture stream: CSR build overlaps GEMM0.
    cudaEventRecord(ev[0], 0);
    cudaStreamWaitEvent(s_aux, ev[0], 0);
    detect_kernel<<<1, 1, 0, s_aux>>>(ei);
    zero_int_kernel<<<(N_NODES + 255) / 256, 256, 0, s_aux>>>(p_cnt, N_NODES);
    hist_kernel<<<NB_EDGE, 256, 0, s_aux>>>(ei, p_cnt);
    blockreduce_kernel<<<NB_SCAN, 256, 0, s_aux>>>(p_cnt, p_bsum);
    scanpart_kernel<<<1, 32, 0, s_aux>>>(p_bsum, NB_SCAN);
    scanfinal_kernel<<<NB_SCAN, 256, 0, s_aux>>>(p_cnt, p_bsum, p_off, p_cur);
    fill_kernel<<<NB_EDGE, 256, 0, s_aux>>>(ei, p_cur, p_csr);
    cudaEventRecord(ev[1], s_aux);

    // Weight splits (main stream, tiny)
    wsplit_kernel<<<64, 256>>>(Wl0, p_whi + 0 * 16384, p_wlo + 0 * 16384, 16384);
    wsplit_kernel<<<64, 256>>>(Wr0, p_whi + 1 * 16384, p_wlo + 1 * 16384, 16384);
    wsplit_kernel<<<64, 256>>>(Wl1, p_whi + 2 * 16384, p_wlo + 2 * 16384, 16384);
    wsplit_kernel<<<64, 256>>>(Wr1, p_whi + 3 * 16384, p_wlo + 3 * 16384, 16384);
    wsplit_kernel<<<32, 256>>>(Wl2, p_whi + 4 * 16384, p_wlo + 4 * 16384, 8192);
    wsplit_kernel<<<32, 256>>>(Wr2, p_whi + 5 * 16384, p_wlo + 5 * 16384, 8192);

    // ---- Layer 0 ----
    gemm_dual_bf16<128, false><<<NB_GEMM, 256, SMEM_GEMM>>>(
        x, nullptr, nullptr, nullptr, nullptr,
        p_whi + 0 * 16384, p_wlo + 0 * 16384, p_whi + 1 * 16384, p_wlo + 1 * 16384,
        p_yl, p_yr);
    cudaStreamWaitEvent(0, ev[1], 0);   // CSR ready before gather
    gather128_agg_kernel<<<NB_G128, 256>>>(p_yl, p_csr, p_off, p_cnt, p_A);

    // ---- Layer 1 (h0 built on the fly from agg0/yr0/b0) ----
    gemm_dual_bf16<128, true><<<NB_GEMM, 256, SMEM_GEMM>>>(
        nullptr, p_A, p_yr, p_cnt, b0,
        p_whi + 2 * 16384, p_wlo + 2 * 16384, p_whi + 3 * 16384, p_wlo + 3 * 16384,
        p_yl, p_yr);
    gather128_agg_kernel<<<NB_G128, 256>>>(p_yl, p_csr, p_off, p_cnt, p_B);

    // ---- Layer 2 (64 out; h1 from agg1/yr1/b1) ----
    gemm_dual_bf16<64, true><<<NB_GEMM, 256, SMEM_GEMM>>>(
        nullptr, p_B, p_yr, p_cnt, b1,
        p_whi + 4 * 16384, p_wlo + 4 * 16384, p_whi + 5 * 16384, p_wlo + 5 * 16384,
        p_yl, p_yr);
    gather64_agg_kernel<<<NB_G64, 256>>>(p_yl, p_csr, p_off, p_cnt, p_A);

    combine64_kernel<<<NB_G64, 256>>>(p_A, p_yr, b2, p_cnt, out);
}

// round 8
// speedup vs baseline: 1.2893x; 1.2893x over previous
#include <cuda_runtime.h>
#include <cuda_bf16.h>
#include <mma.h>
#include <cstdint>

using namespace nvcuda;

// ---------------------------------------------------------------------------
// GraphSAGE 3-layer. Transform-then-aggregate + CSR gather.
// Tensor-core GEMMs via bf16 Markidis split: x*w ~= xh*wh + xh*wl + xl*wh.
// v2: ALL four weight matrices staged in smem per block (R7 read B fragments
// from gmem inside the k-loop -> L1-bound; that was the 530us pathology).
// ---------------------------------------------------------------------------

#define N_NODES 100000
#define N_EDGES 1600000

__device__ float g_yl[(size_t)N_NODES * 128];
__device__ float g_yr[(size_t)N_NODES * 128];
__device__ float g_bufA[(size_t)N_NODES * 128];   // agg
__device__ float g_bufB[(size_t)N_NODES * 128];   // agg
__device__ int   g_cnt[N_NODES];
__device__ int   g_off[N_NODES];
__device__ int   g_cur[N_NODES];
__device__ int   g_csr[N_EDGES];
__device__ int   g_bsum[128];
__device__ int   g_is64;
__device__ __nv_bfloat16 g_whi[6 * 16384];
__device__ __nv_bfloat16 g_wlo[6 * 16384];

// --------------------------- edge dtype probe ------------------------------
__global__ void detect_kernel(const void* ei) {
    const long long* e64 = (const long long*)ei;
    int is64 = 1;
    for (int i = 0; i < 64; i++) {
        long long v = e64[i];
        if (v < 0 || v >= N_NODES) { is64 = 0; break; }
    }
    g_is64 = is64;
}

__device__ __forceinline__ int load_idx(const void* ei, long long pos) {
    if (g_is64) return (int)((const long long*)ei)[pos];
    return ((const int*)ei)[pos];
}

// ------------------------------- CSR build ---------------------------------
__global__ void zero_int_kernel(int* __restrict__ p, int n) {
    int i = blockIdx.x * blockDim.x + threadIdx.x;
    if (i < n) p[i] = 0;
}

__global__ void hist_kernel(const void* __restrict__ ei, int* __restrict__ cnt) {
    int e = blockIdx.x * blockDim.x + threadIdx.x;
    if (e < N_EDGES) {
        int d = load_idx(ei, (long long)N_EDGES + e);
        if ((unsigned)d < N_NODES) atomicAdd(&cnt[d], 1);
    }
}

__global__ void blockreduce_kernel(const int* __restrict__ cnt, int* __restrict__ bsum) {
    __shared__ int sm[256];
    int b = blockIdx.x, t = threadIdx.x;
    int base = b * 1024 + t * 4;
    int s = 0;
    #pragma unroll
    for (int i = 0; i < 4; i++) {
        int idx = base + i;
        if (idx < N_NODES) s += cnt[idx];
    }
    sm[t] = s; __syncthreads();
    for (int st = 128; st > 0; st >>= 1) {
        if (t < st) sm[t] += sm[t + st];
        __syncthreads();
    }
    if (t == 0) bsum[b] = sm[0];
}

__global__ void scanpart_kernel(int* __restrict__ bsum, int nb) {
    if (threadIdx.x == 0) {
        int acc = 0;
        for (int i = 0; i < nb; i++) { int v = bsum[i]; bsum[i] = acc; acc += v; }
    }
}

__global__ void scanfinal_kernel(const int* __restrict__ cnt, const int* __restrict__ bsum,
                                 int* __restrict__ off, int* __restrict__ cur) {
    __shared__ int sm[256];
    int b = blockIdx.x, t = threadIdx.x;
    int base = b * 1024 + t * 4;
    int v[4]; int s = 0;
    #pragma unroll
    for (int i = 0; i < 4; i++) {
        int idx = base + i;
        v[i] = (idx < N_NODES) ? cnt[idx] : 0;
        s += v[i];
    }
    sm[t] = s; __syncthreads();
    for (int st = 1; st < 256; st <<= 1) {
        int x = (t >= st) ? sm[t - st] : 0;
        __syncthreads();
        sm[t] += x;
        __syncthreads();
    }
    int run = sm[t] - s + bsum[b];
    #pragma unroll
    for (int i = 0; i < 4; i++) {
        int idx = base + i;
        if (idx < N_NODES) { off[idx] = run; cur[idx] = run; }
        run += v[i];
    }
}

__global__ void fill_kernel(const void* __restrict__ ei, int* __restrict__ cur,
                            int* __restrict__ csr) {
    int e = blockIdx.x * blockDim.x + threadIdx.x;
    if (e < N_EDGES) {
        int s = load_idx(ei, e);
        int d = load_idx(ei, (long long)N_EDGES + e);
        if ((unsigned)s < N_NODES && (unsigned)d < N_NODES) {
            int p = atomicAdd(&cur[d], 1);
            csr[p] = s;
        }
    }
}

// --------------------- weight split (fp32 -> bf16 hi/lo) -------------------
__global__ void wsplit_kernel(const float* __restrict__ W,
                              __nv_bfloat16* __restrict__ hi,
                              __nv_bfloat16* __restrict__ lo, int n) {
    int i = blockIdx.x * blockDim.x + threadIdx.x;
    if (i < n) {
        float w = W[i];
        __nv_bfloat16 h = __float2bfloat16(w);
        hi[i] = h;
        lo[i] = __float2bfloat16(w - __bfloat162float(h));
    }
}

// ---------------------------------------------------------------------------
// Dual tensor-core GEMM v2: Yl = H@Wl, Yr = H@Wr  (H: [N,128], W: [128,DOUT])
// H is X (PRO=false) or relu(agg/max(deg,1) + yrIn + bias) (PRO=true).
// X split to bf16 hi/lo in smem; ALL 4 weight matrices staged in smem.
// Block: 128 rows, 256 threads (8 warps). 1 block/SM (large smem).
// ---------------------------------------------------------------------------
#define LDXS 136   // X smem leading dim (bf16 elems); 272B rows, 16B aligned

__device__ __forceinline__ void split2(float a, float b, __nv_bfloat162& h2, __nv_bfloat162& l2) {
    __nv_bfloat16 ha = __float2bfloat16(a), hb = __float2bfloat16(b);
    h2 = __nv_bfloat162(ha, hb);
    l2 = __nv_bfloat162(__float2bfloat16(a - __bfloat162float(ha)),
                        __float2bfloat16(b - __bfloat162float(hb)));
}

template <int DOUT, bool PRO>
__global__ __launch_bounds__(256) void gemm_dual_bf16(
    const float* __restrict__ X,
    const float* __restrict__ agg, const float* __restrict__ yrIn,
    const int* __restrict__ cnt, const float* __restrict__ bias,
    const __nv_bfloat16* __restrict__ Wlhi, const __nv_bfloat16* __restrict__ Wllo,
    const __nv_bfloat16* __restrict__ Wrhi, const __nv_bfloat16* __restrict__ Wrlo,
    float* __restrict__ Yl, float* __restrict__ Yr)
{
    constexpr int LDW = DOUT + 8;              // W smem leading dim
    extern __shared__ __nv_bfloat16 smem[];
    __nv_bfloat16* sXhi = smem;                       // [128][LDXS]
    __nv_bfloat16* sXlo = sXhi + 128 * LDXS;          // [128][LDXS]
    __nv_bfloat16* sWlh = sXlo + 128 * LDXS;          // [128][LDW]
    __nv_bfloat16* sWll = sWlh + 128 * LDW;
    __nv_bfloat16* sWrh = sWll + 128 * LDW;
    __nv_bfloat16* sWrl = sWrh + 128 * LDW;

    const int row0 = blockIdx.x * 128;
    const int t = threadIdx.x;

    // ---- stage W (vectorized, 8 bf16 per uint4) ----
    {
        constexpr int C8 = DOUT / 8;               // uint4 chunks per row
        const uint4* gl_h = reinterpret_cast<const uint4*>(Wlhi);
        const uint4* gl_l = reinterpret_cast<const uint4*>(Wllo);
        const uint4* gr_h = reinterpret_cast<const uint4*>(Wrhi);
        const uint4* gr_l = reinterpret_cast<const uint4*>(Wrlo);
        for (int i = t; i < 128 * C8; i += 256) {
            int r = i / C8, c8 = i % C8;
            int so = r * LDW + c8 * 8;
            *reinterpret_cast<uint4*>(&sWlh[so]) = gl_h[i];
            *reinterpret_cast<uint4*>(&sWll[so]) = gl_l[i];
            *reinterpret_cast<uint4*>(&sWrh[so]) = gr_h[i];
            *reinterpret_cast<uint4*>(&sWrl[so]) = gr_l[i];
        }
    }

    // ---- prologue: build H tile, split to bf16 hi/lo ----
    for (int i = t; i < 128 * 32; i += 256) {
        int r = i >> 5, c4 = i & 31;
        int gr = row0 + r;
        float4 v = make_float4(0.f, 0.f, 0.f, 0.f);
        if (gr < N_NODES) {
            if (PRO) {
                float4 a  = reinterpret_cast<const float4*>(agg)[(size_t)gr * 32 + c4];
                float4 yv = reinterpret_cast<const float4*>(yrIn)[(size_t)gr * 32 + c4];
                float4 bb = reinterpret_cast<const float4*>(bias)[c4];
                float dinv = 1.0f / fmaxf((float)cnt[gr], 1.0f);
                v.x = fmaxf(a.x * dinv + yv.x + bb.x, 0.f);
                v.y = fmaxf(a.y * dinv + yv.y + bb.y, 0.f);
                v.z = fmaxf(a.z * dinv + yv.z + bb.z, 0.f);
                v.w = fmaxf(a.w * dinv + yv.w + bb.w, 0.f);
            } else {
                v = reinterpret_cast<const float4*>(X + (size_t)gr * 128)[c4];
            }
        }
        __nv_bfloat162 h0, l0, h1, l1;
        split2(v.x, v.y, h0, l0);
        split2(v.z, v.w, h1, l1);
        int base = r * LDXS + c4 * 4;
        *reinterpret_cast<__nv_bfloat162*>(&sXhi[base])     = h0;
        *reinterpret_cast<__nv_bfloat162*>(&sXhi[base + 2]) = h1;
        *reinterpret_cast<__nv_bfloat162*>(&sXlo[base])     = l0;
        *reinterpret_cast<__nv_bfloat162*>(&sXlo[base + 2]) = l1;
    }
    __syncthreads();

    // ---- warp tiling ----
    constexpr int WN = DOUT / 64;          // warps along n (2 or 1)
    constexpr int WM = 8 / WN;             // warps along m (4 or 8)
    constexpr int MFRAG = 128 / (WM * 16); // 2 or 1
    const int warp = t >> 5;
    const int wm = warp % WM;
    const int wn = warp / WM;
    const int mbase = wm * MFRAG * 16;
    const int nbase = wn * 64;

    wmma::fragment<wmma::accumulator, 16, 16, 16, float> accl[MFRAG][4], accr[MFRAG][4];
    #pragma unroll
    for (int mf = 0; mf < MFRAG; mf++)
        #pragma unroll
        for (int nf = 0; nf < 4; nf++) {
            wmma::fill_fragment(accl[mf][nf], 0.0f);
            wmma::fill_fragment(accr[mf][nf], 0.0f);
        }

    #pragma unroll
    for (int k = 0; k < 128; k += 16) {
        wmma::fragment<wmma::matrix_a, 16, 16, 16, __nv_bfloat16, wmma::row_major> ahi[MFRAG], alo[MFRAG];
        #pragma unroll
        for (int mf = 0; mf < MFRAG; mf++) {
            wmma::load_matrix_sync(ahi[mf], &sXhi[(mbase + mf * 16) * LDXS + k], LDXS);
            wmma::load_matrix_sync(alo[mf], &sXlo[(mbase + mf * 16) * LDXS + k], LDXS);
        }
        #pragma unroll
        for (int nf = 0; nf < 4; nf++) {
            int n0 = nbase + nf * 16;
            wmma::fragment<wmma::matrix_b, 16, 16, 16, __nv_bfloat16, wmma::row_major> bhl, bll, bhr, blr;
            wmma::load_matrix_sync(bhl, &sWlh[k * LDW + n0], LDW);
            wmma::load_matrix_sync(bll, &sWll[k * LDW + n0], LDW);
            wmma::load_matrix_sync(bhr, &sWrh[k * LDW + n0], LDW);
            wmma::load_matrix_sync(blr, &sWrl[k * LDW + n0], LDW);
            #pragma unroll
            for (int mf = 0; mf < MFRAG; mf++) {
                wmma::mma_sync(accl[mf][nf], ahi[mf], bhl, accl[mf][nf]);
                wmma::mma_sync(accl[mf][nf], ahi[mf], bll, accl[mf][nf]);
                wmma::mma_sync(accl[mf][nf], alo[mf], bhl, accl[mf][nf]);
                wmma::mma_sync(accr[mf][nf], ahi[mf], bhr, accr[mf][nf]);
                wmma::mma_sync(accr[mf][nf], ahi[mf], blr, accr[mf][nf]);
                wmma::mma_sync(accr[mf][nf], alo[mf], bhr, accr[mf][nf]);
            }
        }
    }

    // ---- store (N_NODES = 100000 is 16-aligned -> fragment-level guard) ----
    #pragma unroll
    for (int mf = 0; mf < MFRAG; mf++) {
        int grow = row0 + mbase + mf * 16;
        if (grow < N_NODES) {
            #pragma unroll
            for (int nf = 0; nf < 4; nf++) {
                wmma::store_matrix_sync(Yl + (size_t)grow * DOUT + nbase + nf * 16,
                                        accl[mf][nf], DOUT, wmma::mem_row_major);
                wmma::store_matrix_sync(Yr + (size_t)grow * DOUT + nbase + nf * 16,
                                        accr[mf][nf], DOUT, wmma::mem_row_major);
            }
        }
    }
}

// ---------------------------------------------------------------------------
// Agg-only gathers: agg[n] = sum_{s in N(n)} yl[s]
// ---------------------------------------------------------------------------
__global__ __launch_bounds__(256) void gather128_agg_kernel(
    const float* __restrict__ yl,
    const int* __restrict__ csr, const int* __restrict__ off,
    const int* __restrict__ cnt, float* __restrict__ agg)
{
    int warp = (blockIdx.x * 256 + threadIdx.x) >> 5;
    int lane = threadIdx.x & 31;
    if (warp >= N_NODES) return;

    const int c = cnt[warp];
    const int o = off[warp];
    const float4* __restrict__ yl4 = reinterpret_cast<const float4*>(yl);

    float4 acc = make_float4(0.f, 0.f, 0.f, 0.f);
    int j = 0;
    for (; j + 4 <= c; j += 4) {
        int s0 = csr[o + j + 0];
        int s1 = csr[o + j + 1];
        int s2 = csr[o + j + 2];
        int s3 = csr[o + j + 3];
        float4 a0 = yl4[(size_t)s0 * 32 + lane];
        float4 a1 = yl4[(size_t)s1 * 32 + lane];
        float4 a2 = yl4[(size_t)s2 * 32 + lane];
        float4 a3 = yl4[(size_t)s3 * 32 + lane];
        acc.x += a0.x + a1.x + a2.x + a3.x;
        acc.y += a0.y + a1.y + a2.y + a3.y;
        acc.z += a0.z + a1.z + a2.z + a3.z;
        acc.w += a0.w + a1.w + a2.w + a3.w;
    }
    for (; j < c; j++) {
        int s = csr[o + j];
        float4 a = yl4[(size_t)s * 32 + lane];
        acc.x += a.x; acc.y += a.y; acc.z += a.z; acc.w += a.w;
    }
    reinterpret_cast<float4*>(agg)[(size_t)warp * 32 + lane] = acc;
}

__global__ __launch_bounds__(256) void gather64_agg_kernel(
    const float* __restrict__ yl,
    const int* __restrict__ csr, const int* __restrict__ off,
    const int* __restrict__ cnt, float* __restrict__ agg)
{
    int node = (blockIdx.x * 256 + threadIdx.x) >> 4;
    int sub  = threadIdx.x & 15;
    if (node >= N_NODES) return;

    const int c = cnt[node];
    const int o = off[node];
    const float4* __restrict__ yl4 = reinterpret_cast<const float4*>(yl);

    float4 acc = make_float4(0.f, 0.f, 0.f, 0.f);
    int j = 0;
    for (; j + 4 <= c; j += 4) {
        int s0 = csr[o + j + 0];
        int s1 = csr[o + j + 1];
        int s2 = csr[o + j + 2];
        int s3 = csr[o + j + 3];
        float4 a0 = yl4[(size_t)s0 * 16 + sub];
        float4 a1 = yl4[(size_t)s1 * 16 + sub];
        float4 a2 = yl4[(size_t)s2 * 16 + sub];
        float4 a3 = yl4[(size_t)s3 * 16 + sub];
        acc.x += a0.x + a1.x + a2.x + a3.x;
        acc.y += a0.y + a1.y + a2.y + a3.y;
        acc.z += a0.z + a1.z + a2.z + a3.z;
        acc.w += a0.w + a1.w + a2.w + a3.w;
    }
    for (; j < c; j++) {
        int s = csr[o + j];
        float4 a = yl4[(size_t)s * 16 + sub];
        acc.x += a.x; acc.y += a.y; acc.z += a.z; acc.w += a.w;
    }
    reinterpret_cast<float4*>(agg)[(size_t)node * 16 + sub] = acc;
}

// ---------------------------------------------------------------------------
__global__ __launch_bounds__(256) void combine64_kernel(
    const float* __restrict__ agg, const float* __restrict__ yr,
    const float* __restrict__ b, const int* __restrict__ cnt,
    float* __restrict__ out)
{
    int i = blockIdx.x * blockDim.x + threadIdx.x;
    if (i >= N_NODES * 16) return;
    int node = i >> 4;
    int c4 = i & 15;

    float dinv = 1.0f / fmaxf((float)cnt[node], 1.0f);
    float4 a = reinterpret_cast<const float4*>(agg)[i];
    float4 r = reinterpret_cast<const float4*>(yr)[i];
    float4 bb = reinterpret_cast<const float4*>(b)[c4];

    float4 o;
    o.x = a.x * dinv + r.x + bb.x;
    o.y = a.y * dinv + r.y + bb.y;
    o.z = a.z * dinv + r.z + bb.z;
    o.w = a.w * dinv + r.w + bb.w;
    reinterpret_cast<float4*>(out)[i] = o;
}

// ---------------------------------------------------------------------------
extern "C" void kernel_launch(void* const* d_in, const int* in_sizes, int n_in,
                              void* d_out, int out_size)
{
    const float* x   = (const float*)d_in[0];
    const void*  ei  = d_in[1];
    const float* Wl0 = (const float*)d_in[2];
    const float* Wr0 = (const float*)d_in[3];
    const float* b0  = (const float*)d_in[4];
    const float* Wl1 = (const float*)d_in[5];
    const float* Wr1 = (const float*)d_in[6];
    const float* b1  = (const float*)d_in[7];
    const float* Wl2 = (const float*)d_in[8];
    const float* Wr2 = (const float*)d_in[9];
    const float* b2  = (const float*)d_in[10];
    float* out = (float*)d_out;

    const int SMEM_X    = 128 * LDXS * 2 * (int)sizeof(__nv_bfloat16);          // 69632
    const int SMEM_128  = SMEM_X + 4 * 128 * (128 + 8) * (int)sizeof(__nv_bfloat16); // 208896
    const int SMEM_64   = SMEM_X + 4 * 128 * (64 + 8)  * (int)sizeof(__nv_bfloat16); // 143360

    static float *p_yl = nullptr, *p_yr = nullptr, *p_A = nullptr, *p_B = nullptr;
    static int *p_cnt = nullptr, *p_off = nullptr, *p_cur = nullptr, *p_csr = nullptr, *p_bsum = nullptr;
    static __nv_bfloat16 *p_whi = nullptr, *p_wlo = nullptr;
    static cudaStream_t s_aux = nullptr;
    static cudaEvent_t ev[4];
    if (!p_yl) {
        cudaGetSymbolAddress((void**)&p_yl,   g_yl);
        cudaGetSymbolAddress((void**)&p_yr,   g_yr);
        cudaGetSymbolAddress((void**)&p_A,    g_bufA);
        cudaGetSymbolAddress((void**)&p_B,    g_bufB);
        cudaGetSymbolAddress((void**)&p_cnt,  g_cnt);
        cudaGetSymbolAddress((void**)&p_off,  g_off);
        cudaGetSymbolAddress((void**)&p_cur,  g_cur);
        cudaGetSymbolAddress((void**)&p_csr,  g_csr);
        cudaGetSymbolAddress((void**)&p_bsum, g_bsum);
        cudaGetSymbolAddress((void**)&p_whi,  g_whi);
        cudaGetSymbolAddress((void**)&p_wlo,  g_wlo);
        cudaStreamCreateWithFlags(&s_aux, cudaStreamNonBlocking);
        for (int i = 0; i < 4; i++)
            cudaEventCreateWithFlags(&ev[i], cudaEventDisableTiming);
        cudaFuncSetAttribute(gemm_dual_bf16<128, false>,
                             cudaFuncAttributeMaxDynamicSharedMemorySize, SMEM_128);
        cudaFuncSetAttribute(gemm_dual_bf16<128, true>,
                             cudaFuncAttributeMaxDynamicSharedMemorySize, SMEM_128);
        cudaFuncSetAttribute(gemm_dual_bf16<64, true>,
                             cudaFuncAttributeMaxDynamicSharedMemorySize, SMEM_64);
    }

    const int NB_GEMM  = (N_NODES + 127) / 128;          // 782
    const int NB_SCAN  = (N_NODES + 1023) / 1024;
    const int NB_EDGE  = (N_EDGES + 255) / 256;
    const int NB_G128  = (N_NODES * 32 + 255) / 256;
    const int NB_G64   = (N_NODES * 16 + 255) / 256;

    // Fork aux stream off the capture stream: CSR build overlaps GEMM0.
    cudaEventRecord(ev[0], 0);
    cudaStreamWaitEvent(s_aux, ev[0], 0);
    detect_kernel<<<1, 1, 0, s_aux>>>(ei);
    zero_int_kernel<<<(N_NODES + 255) / 256, 256, 0, s_aux>>>(p_cnt, N_NODES);
    hist_kernel<<<NB_EDGE, 256, 0, s_aux>>>(ei, p_cnt);
    blockreduce_kernel<<<NB_SCAN, 256, 0, s_aux>>>(p_cnt, p_bsum);
    scanpart_kernel<<<1, 32, 0, s_aux>>>(p_bsum, NB_SCAN);
    scanfinal_kernel<<<NB_SCAN, 256, 0, s_aux>>>(p_cnt, p_bsum, p_off, p_cur);
    fill_kernel<<<NB_EDGE, 256, 0, s_aux>>>(ei, p_cur, p_csr);
    cudaEventRecord(ev[1], s_aux);

    // Weight splits (main stream, tiny)
    wsplit_kernel<<<64, 256>>>(Wl0, p_whi + 0 * 16384, p_wlo + 0 * 16384, 16384);
    wsplit_kernel<<<64, 256>>>(Wr0, p_whi + 1 * 16384, p_wlo + 1 * 16384, 16384);
    wsplit_kernel<<<64, 256>>>(Wl1, p_whi + 2 * 16384, p_wlo + 2 * 16384, 16384);
    wsplit_kernel<<<64, 256>>>(Wr1, p_whi + 3 * 16384, p_wlo + 3 * 16384, 16384);
    wsplit_kernel<<<32, 256>>>(Wl2, p_whi + 4 * 16384, p_wlo + 4 * 16384, 8192);
    wsplit_kernel<<<32, 256>>>(Wr2, p_whi + 5 * 16384, p_wlo + 5 * 16384, 8192);

    // ---- Layer 0 ----
    gemm_dual_bf16<128, false><<<NB_GEMM, 256, SMEM_128>>>(
        x, nullptr, nullptr, nullptr, nullptr,
        p_whi + 0 * 16384, p_wlo + 0 * 16384, p_whi + 1 * 16384, p_wlo + 1 * 16384,
        p_yl, p_yr);
    cudaStreamWaitEvent(0, ev[1], 0);   // CSR ready before gather
    gather128_agg_kernel<<<NB_G128, 256>>>(p_yl, p_csr, p_off, p_cnt, p_A);

    // ---- Layer 1 (h0 built on the fly from agg0/yr0/b0) ----
    gemm_dual_bf16<128, true><<<NB_GEMM, 256, SMEM_128>>>(
        nullptr, p_A, p_yr, p_cnt, b0,
        p_whi + 2 * 16384, p_wlo + 2 * 16384, p_whi + 3 * 16384, p_wlo + 3 * 16384,
        p_yl, p_yr);
    gather128_agg_kernel<<<NB_G128, 256>>>(p_yl, p_csr, p_off, p_cnt, p_B);

    // ---- Layer 2 (64 out; h1 from agg1/yr1/b1) ----
    gemm_dual_bf16<64, true><<<NB_GEMM, 256, SMEM_64>>>(
        nullptr, p_B, p_yr, p_cnt, b1,
        p_whi + 4 * 16384, p_wlo + 4 * 16384, p_whi + 5 * 16384, p_wlo + 5 * 16384,
        p_yl, p_yr);
    gather64_agg_kernel<<<NB_G64, 256>>>(p_yl, p_csr, p_off, p_cnt, p_A);

    combine64_kernel<<<NB_G64, 256>>>(p_A, p_yr, b2, p_cnt, out);
}